// round 1
// baseline (speedup 1.0000x reference)
#include <cuda_runtime.h>
#include <math.h>

// ============================================================================
// AUC_86990267613596: streaming AUC over sigmoid(output) with 30 thresholds.
// Strategy: x-domain thresholds (no transcendentals), shared-mem LUT binning,
// bit-sliced ballot histogram (register accumulation, ~zero atomics).
// ============================================================================

#define LUTN    1024
#define LUT_LO  (-3.5f)
#define LUT_HI  (3.5f)
#define NBINS   31          // bins 0..30 (bin 30 provably empty, kept for safety)

struct __align__(8) LutE { float th; int bin; };

__device__ LutE         g_lut[LUTN];
__device__ unsigned int g_hist_all[32];
__device__ unsigned int g_hist_t[32];

// ---------------------------------------------------------------------------
// Init: zero global hist scratch, build x-domain thresholds + LUT.
// Thresholds: ths_asc[k] = fp32((k+1)/30); x-threshold = logit(th) in double.
// LUT cell i holds (base_bin at cell left edge minus slop, next threshold).
// Guarantee: any x mapping to cell i has true bin in {base, base+1}, and the
// single compare x >= th resolves it (<=1 threshold per widened cell).
// ---------------------------------------------------------------------------
__global__ void auc_init_kernel() {
    int t = threadIdx.x;
    if (t < 32) { g_hist_all[t] = 0u; g_hist_t[t] = 0u; }

    float xt[30];
#pragma unroll 1
    for (int b = 0; b < 30; b++) {
        float th = (float)(b + 1) / 30.0f;
        if (b == 29) xt[b] = __int_as_float(0x7f800000);   // th = 1.0 -> +inf
        else         xt[b] = (float)log((double)th / (1.0 - (double)th));
    }
    for (int i = t; i < LUTN; i += blockDim.x) {
        double xl = (double)LUT_LO
                  + (double)i * ((double)LUT_HI - (double)LUT_LO) / (double)LUTN
                  - 1e-3;                                   // conservative slop
        int L = 0;
#pragma unroll 1
        for (int b = 0; b < 30; b++) if ((double)xt[b] <= xl) L++;
        // L <= 29 always (xt[29] = +inf never <= finite xl)
        g_lut[i].th  = xt[L];
        g_lut[i].bin = L;
    }
}

// ---------------------------------------------------------------------------
// Main: persistent grid, float4 loads, LUT binning, bit-sliced ballot counts.
// Each lane owns bin == lane_id in a register counter; padding lanes use
// bin 31 which is never read back.
// ---------------------------------------------------------------------------
__global__ void __launch_bounds__(256) auc_main_kernel(
    const float* __restrict__ outp, const int* __restrict__ target,
    int total4, int C)
{
    __shared__ LutE         s_lut[LUTN];     // 8 KB
    __shared__ unsigned int s_ha[32];
    __shared__ unsigned int s_ht[32];

    const int tid = threadIdx.x;
    if (tid < 32) { s_ha[tid] = 0u; s_ht[tid] = 0u; }
    for (int i = tid; i < LUTN; i += blockDim.x) s_lut[i] = g_lut[i];
    __syncthreads();

    const unsigned lane = tid & 31;
    const unsigned e0 = (lane & 1u)  ? 0xFFFFFFFFu : 0u;
    const unsigned e1 = (lane & 2u)  ? 0xFFFFFFFFu : 0u;
    const unsigned e2 = (lane & 4u)  ? 0xFFFFFFFFu : 0u;
    const unsigned e3 = (lane & 8u)  ? 0xFFFFFFFFu : 0u;
    const unsigned e4 = (lane & 16u) ? 0xFFFFFFFFu : 0u;

    const float scale = (float)LUTN / (LUT_HI - LUT_LO);
    const float off   = -LUT_LO * scale;

    const float4* __restrict__ out4 = (const float4*)outp;

    unsigned cnt = 0;                         // count of elements with bin==lane
    const int stride = gridDim.x * blockDim.x;
    const int g      = blockIdx.x * blockDim.x + tid;
    const int gw     = g - (int)lane;         // warp-uniform base index

    for (int vb = gw; vb < total4; vb += stride) {
        const int v = vb + (int)lane;
        const bool active = (v < total4);
        int b0 = 31, b1 = 31, b2 = 31, b3 = 31;

        if (active) {
            const float4 d = out4[v];
            const int e   = v << 2;           // first element index of this float4
            const int row = e / C;
            const int col = e - row * C;
            const int ts  = target[row] - col;  // in [0,3] iff true elem in this float4

            {   // element 0
                float x  = d.x;
                float fi = fminf(fmaxf(fmaf(x, scale, off), 0.0f), (float)(LUTN - 1));
                LutE en  = s_lut[(int)fi];
                b0 = en.bin + (x >= en.th ? 1 : 0);
                if (ts == 0) atomicAdd(&s_ht[b0], 1u);
            }
            {   // element 1
                float x  = d.y;
                float fi = fminf(fmaxf(fmaf(x, scale, off), 0.0f), (float)(LUTN - 1));
                LutE en  = s_lut[(int)fi];
                b1 = en.bin + (x >= en.th ? 1 : 0);
                if (ts == 1) atomicAdd(&s_ht[b1], 1u);
            }
            {   // element 2
                float x  = d.z;
                float fi = fminf(fmaxf(fmaf(x, scale, off), 0.0f), (float)(LUTN - 1));
                LutE en  = s_lut[(int)fi];
                b2 = en.bin + (x >= en.th ? 1 : 0);
                if (ts == 2) atomicAdd(&s_ht[b2], 1u);
            }
            {   // element 3
                float x  = d.w;
                float fi = fminf(fmaxf(fmaf(x, scale, off), 0.0f), (float)(LUTN - 1));
                LutE en  = s_lut[(int)fi];
                b3 = en.bin + (x >= en.th ? 1 : 0);
                if (ts == 3) atomicAdd(&s_ht[b3], 1u);
            }
        }

        // Bit-sliced per-warp histogram: 5 ballots per 32 elements per slot.
        // All lanes (incl. padding) participate; padding bin=31 is ignored.
#pragma unroll
        for (int j = 0; j < 4; j++) {
            const unsigned bb = (unsigned)(j == 0 ? b0 : j == 1 ? b1 : j == 2 ? b2 : b3);
            const unsigned p0 = __ballot_sync(0xFFFFFFFFu, bb & 1u);
            const unsigned p1 = __ballot_sync(0xFFFFFFFFu, bb & 2u);
            const unsigned p2 = __ballot_sync(0xFFFFFFFFu, bb & 4u);
            const unsigned p3 = __ballot_sync(0xFFFFFFFFu, bb & 8u);
            const unsigned p4 = __ballot_sync(0xFFFFFFFFu, bb & 16u);
            const unsigned m  = ~((p0 ^ e0) | (p1 ^ e1) | (p2 ^ e2) |
                                  (p3 ^ e3) | (p4 ^ e4));
            cnt += __popc(m);
        }
    }

    atomicAdd(&s_ha[lane], cnt);
    __syncthreads();
    if (tid < 32) {
        unsigned a = s_ha[tid], t = s_ht[tid];
        if (a) atomicAdd(&g_hist_all[tid], a);
        if (t) atomicAdd(&g_hist_t[tid],  t);
    }
}

// ---------------------------------------------------------------------------
// Finalize: tiny scalar AUC from the 31-bin histograms (mirrors reference).
// ---------------------------------------------------------------------------
__global__ void auc_finalize_kernel(float* __restrict__ out, int total) {
    if (threadIdx.x != 0 || blockIdx.x != 0) return;

    double t[31], a[31], trues = 0.0;
#pragma unroll 1
    for (int b = 0; b < 31; b++) {
        t[b] = (double)g_hist_t[b];
        a[b] = (double)g_hist_all[b];
        trues += t[b];
    }
    const double falses = (double)total - trues;

    double tp_asc[30], fp_asc[30];
    double ct = 0.0, cf = 0.0;
#pragma unroll 1
    for (int k = 0; k < 30; k++) {
        ct += t[k];
        cf += (a[k] - t[k]);
        tp_asc[k] = trues  - ct;
        fp_asc[k] = falses - cf;
    }

    const double dt = trues  + 1e-8;
    const double df = falses + 1e-8;
    double area = 0.0, pt = 0.0, pf = 0.0;   // tprs[0] = fprs[0] = 0
#pragma unroll 1
    for (int i = 0; i < 30; i++) {
        const double tt = tp_asc[29 - i] / dt;
        const double ff = fp_asc[29 - i] / df;
        const double w  = fabs(ff - pf);
        const double mn = fmin(tt, pt);
        const double mx = fmax(tt, pt);
        area += w * mn + 0.5 * w * (mx - mn);
        pt = tt; pf = ff;
    }
    out[0] = (float)area;
}

// ---------------------------------------------------------------------------
extern "C" void kernel_launch(void* const* d_in, const int* in_sizes, int n_in,
                              void* d_out, int out_size) {
    const float* outp   = (const float*)d_in[0];
    const int*   target = (const int*)d_in[1];
    const int total = in_sizes[0];          // N * C = 32,000,000
    const int n     = in_sizes[1];          // N = 500,000
    const int C     = total / n;            // 64
    const int total4 = total / 4;           // C % 4 == 0

    auc_init_kernel<<<1, 256>>>();
    auc_main_kernel<<<1216, 256>>>(outp, target, total4, C);
    auc_finalize_kernel<<<1, 32>>>((float*)d_out, total);
}

// round 3
// speedup vs baseline: 1.6763x; 1.6763x over previous
#include <cuda_runtime.h>
#include <math.h>

// ============================================================================
// AUC_86990267613596 — Round 2 (resubmit; R2 never benched due to broker timeout)
// sigmoid+searchsorted AUC == x-domain threshold binning (logit thresholds).
// Hot loop: conflict-free 32x lane-replicated packed LUT (4B: threshold fp32
// with its 5 low mantissa bits holding the base bin), bit-sliced ballot
// histogram in registers. True-class elements handled in a balanced pre-pass.
// ============================================================================

#define LUTN        256
#define TPB         256
#define GRID        592          // 148 SMs x 4 blocks, single wave
#define FULL_MASK   0xFFFFFFFFu

// x-domain thresholds: xt[k] = logit((k+1)/30), k = 0..28 (k=29 -> +inf).
__constant__ float c_xt[29] = {
    -3.3672958299864741f, -2.6390572896531649f, -2.1972245773362196f,
    -1.8718021769015914f, -1.6094379124341003f, -1.3862943611198906f,
    -1.1895841068359301f, -1.0116009116784801f, -0.8472978204251098f,
    -0.6931471805599453f, -0.5465437063680696f, -0.4054651081081644f,
    -0.2682639865946793f, -0.1335314325866163f,  0.0f,
     0.1335314325866163f,  0.2682639865946793f,  0.4054651081081644f,
     0.5465437063680696f,  0.6931471805599453f,  0.8472978204251098f,
     1.0116009116784801f,  1.1895841068359301f,  1.3862943611198906f,
     1.6094379124341003f,  1.8718021769015914f,  2.1972245773362196f,
     2.6390572896531649f,  3.3672958299864741f
};

__device__ unsigned int g_hist_all[32];
__device__ unsigned int g_hist_t[32];

// ---------------------------------------------------------------------------
__global__ void auc_init_kernel() {
    int t = threadIdx.x;
    if (t < 32) { g_hist_all[t] = 0u; g_hist_t[t] = 0u; }
}

// ---------------------------------------------------------------------------
// Bit-sliced warp histogram: lane L accumulates #elements whose bin == L.
// bb in [0,31]; padding uses bb = 31 (bin 31 is never read back).
__device__ __forceinline__ unsigned match_cnt(
    unsigned bb, unsigned e0, unsigned e1, unsigned e2, unsigned e3, unsigned e4)
{
    unsigned p0 = __ballot_sync(FULL_MASK, (bb & 1u)  != 0u);
    unsigned p1 = __ballot_sync(FULL_MASK, (bb & 2u)  != 0u);
    unsigned p2 = __ballot_sync(FULL_MASK, (bb & 4u)  != 0u);
    unsigned p3 = __ballot_sync(FULL_MASK, (bb & 8u)  != 0u);
    unsigned p4 = __ballot_sync(FULL_MASK, (bb & 16u) != 0u);
    return __popc(~((p0 ^ e0) | (p1 ^ e1) | (p2 ^ e2) | (p3 ^ e3) | (p4 ^ e4)));
}

// Packed-LUT binning: entry = threshold float with low 5 mantissa bits = base.
__device__ __forceinline__ unsigned calc_bin(float x, const unsigned* __restrict__ lutl)
{
    float fi = fminf(fmaxf(fmaf(x, 256.0f / 7.0f, 128.0f), 0.0f), 255.0f);
    int idx = (int)fi;
    unsigned e = lutl[idx << 5];                       // conflict-free (bank==lane)
    return (e & 31u) + ((x >= __uint_as_float(e)) ? 1u : 0u);
}

// ---------------------------------------------------------------------------
__global__ void __launch_bounds__(TPB) auc_main_kernel(
    const float* __restrict__ outp, const int* __restrict__ target,
    int total4, int n, int C)
{
    __shared__ unsigned s_lut[LUTN * 32];   // 32 KB, 32x lane-replicated
    __shared__ unsigned s_ha[32];

    const int tid  = threadIdx.x;
    const unsigned lane = tid & 31u;
    if (tid < 32) s_ha[tid] = 0u;

    // Build packed LUT (one cell per thread), store 32 replicas swizzled.
    {
        int i = tid;                                   // LUTN == TPB
        float cl = -3.5f + (float)i * (7.0f / 256.0f);
        int base = 0;
#pragma unroll
        for (int k = 0; k < 29; k++) base += (c_xt[k] <= cl) ? 1 : 0;
        unsigned pb;
        if (base < 29) pb = (__float_as_uint(c_xt[base]) & 0xFFFFFFE0u) | (unsigned)base;
        else           pb = 0x7F800000u | 29u;         // NaN: x>=NaN false, bin=29
#pragma unroll
        for (int r = 0; r < 32; r++)
            s_lut[(i << 5) + ((r + i) & 31)] = pb;     // swizzled: conflict-free STS
    }

    const unsigned e0 = (lane & 1u)  ? FULL_MASK : 0u;
    const unsigned e1 = (lane & 2u)  ? FULL_MASK : 0u;
    const unsigned e2 = (lane & 4u)  ? FULL_MASK : 0u;
    const unsigned e3 = (lane & 8u)  ? FULL_MASK : 0u;
    const unsigned e4 = (lane & 16u) ? FULL_MASK : 0u;

    // ---- True-class pre-pass: one gathered element per row, balanced over grid.
    unsigned cnt_t = 0;
    {
        const int T   = GRID * TPB;
        const int rw0 = (blockIdx.x * TPB + tid) - (int)lane;
        for (int rw = rw0; rw < n; rw += T) {
            const int r = rw + (int)lane;
            unsigned bb = 31u;
            if (r < n) {
                const int   t = target[r];
                const float x = outp[r * C + t];
                unsigned b = 0;
#pragma unroll
                for (int k = 0; k < 29; k++) b += (x >= c_xt[k]) ? 1u : 0u;
                bb = b;
            }
            cnt_t += match_cnt(bb, e0, e1, e2, e3, e4);
        }
    }

    __syncthreads();                                   // LUT ready

    // ---- Main streaming pass over all elements (float4, unroll 2 for MLP).
    const unsigned* __restrict__ lutl = s_lut + lane;
    const float4*   __restrict__ out4 = (const float4*)outp;

    unsigned cnt = 0;
    const int stride4 = GRID * TPB;
    const int gw      = (blockIdx.x * TPB + tid) - (int)lane;

    for (int vb = gw; vb < total4; vb += 2 * stride4) {
        const int v0 = vb + (int)lane;
        const int v1 = v0 + stride4;
        unsigned b[8];
#pragma unroll
        for (int j = 0; j < 8; j++) b[j] = 31u;

        if (v0 < total4) {
            const float4 d = out4[v0];
            b[0] = calc_bin(d.x, lutl);
            b[1] = calc_bin(d.y, lutl);
            b[2] = calc_bin(d.z, lutl);
            b[3] = calc_bin(d.w, lutl);
        }
        if (v1 < total4) {
            const float4 d = out4[v1];
            b[4] = calc_bin(d.x, lutl);
            b[5] = calc_bin(d.y, lutl);
            b[6] = calc_bin(d.z, lutl);
            b[7] = calc_bin(d.w, lutl);
        }
#pragma unroll
        for (int j = 0; j < 8; j++)
            cnt += match_cnt(b[j], e0, e1, e2, e3, e4);
    }

    atomicAdd(&s_ha[lane], cnt);
    if (cnt_t) atomicAdd(&g_hist_t[lane], cnt_t);
    __syncthreads();
    if (tid < 32) {
        unsigned a = s_ha[tid];
        if (a) atomicAdd(&g_hist_all[tid], a);
    }
}

// ---------------------------------------------------------------------------
__global__ void auc_finalize_kernel(float* __restrict__ out, int total) {
    if (threadIdx.x != 0) return;

    double t[31], a[31], trues = 0.0;
#pragma unroll 1
    for (int b = 0; b < 31; b++) {
        t[b] = (double)g_hist_t[b];
        a[b] = (double)g_hist_all[b];
        trues += t[b];
    }
    const double falses = (double)total - trues;

    double tp_asc[30], fp_asc[30];
    double ct = 0.0, cf = 0.0;
#pragma unroll 1
    for (int k = 0; k < 30; k++) {
        ct += t[k];
        cf += (a[k] - t[k]);
        tp_asc[k] = trues  - ct;
        fp_asc[k] = falses - cf;
    }

    const double dt = trues  + 1e-8;
    const double df = falses + 1e-8;
    double area = 0.0, pt = 0.0, pf = 0.0;
#pragma unroll 1
    for (int i = 0; i < 30; i++) {
        const double tt = tp_asc[29 - i] / dt;
        const double ff = fp_asc[29 - i] / df;
        const double w  = fabs(ff - pf);
        const double mn = fmin(tt, pt);
        const double mx = fmax(tt, pt);
        area += w * mn + 0.5 * w * (mx - mn);
        pt = tt; pf = ff;
    }
    out[0] = (float)area;
}

// ---------------------------------------------------------------------------
extern "C" void kernel_launch(void* const* d_in, const int* in_sizes, int n_in,
                              void* d_out, int out_size) {
    const float* outp   = (const float*)d_in[0];
    const int*   target = (const int*)d_in[1];
    const int total  = in_sizes[0];      // N*C = 32,000,000
    const int n      = in_sizes[1];      // N   = 500,000
    const int C      = total / n;        // 64
    const int total4 = total / 4;

    auc_init_kernel<<<1, 64>>>();
    auc_main_kernel<<<GRID, TPB>>>(outp, target, total4, n, C);
    auc_finalize_kernel<<<1, 32>>>((float*)d_out, total);
}

// round 7
// speedup vs baseline: 2.6757x; 1.5962x over previous
#include <cuda_runtime.h>

// ============================================================================
// AUC_86990267613596 — Round 7 (R6 resubmit; compute-then-RMW partition)
// x-domain logit thresholds; packed conflict-free replicated LUT for binning;
// per-(warp,lane)-column shared histogram RMW (no ballots, no atomics, no
// warp syncs in hot loop). 4 unconditional back-to-back LDG.128 per iter;
// all 16 bins computed before the 16 smem RMWs.
// ============================================================================

#define LUTN   256
#define TPB    256
#define NWARPS 8
#define GRID   444            // 148 SMs x 3 blocks (65.7KB smem each)
#define HIST_WORDS (NWARPS * 32 * 32)                    // 8192
#define SMEM_BYTES ((LUTN * 32 + HIST_WORDS + 32) * 4)   // 65,664 B

// xt[k] = logit((k+1)/30), k = 0..28 (k=29 -> +inf, handled as NaN sentinel).
__constant__ float c_xt[29] = {
    -3.3672958299864741f, -2.6390572896531649f, -2.1972245773362196f,
    -1.8718021769015914f, -1.6094379124341003f, -1.3862943611198906f,
    -1.1895841068359301f, -1.0116009116784801f, -0.8472978204251098f,
    -0.6931471805599453f, -0.5465437063680696f, -0.4054651081081644f,
    -0.2682639865946793f, -0.1335314325866163f,  0.0f,
     0.1335314325866163f,  0.2682639865946793f,  0.4054651081081644f,
     0.5465437063680696f,  0.6931471805599453f,  0.8472978204251098f,
     1.0116009116784801f,  1.1895841068359301f,  1.3862943611198906f,
     1.6094379124341003f,  1.8718021769015914f,  2.1972245773362196f,
     2.6390572896531649f,  3.3672958299864741f
};

__device__ unsigned g_hist_all[32];
__device__ unsigned g_hist_t[32];

// ---------------------------------------------------------------------------
__global__ void auc_init_kernel() {
    int t = threadIdx.x;
    if (t < 32) { g_hist_all[t] = 0u; g_hist_t[t] = 0u; }
}

// Packed-LUT binning: entry = threshold fp32 with low 5 mantissa bits = base bin.
__device__ __forceinline__ unsigned calc_bin(float x, const unsigned* __restrict__ lutl)
{
    float fi = fminf(fmaxf(fmaf(x, 256.0f / 7.0f, 128.0f), 0.0f), 255.0f);
    unsigned e = lutl[(int)fi << 5];               // bank == lane: conflict-free
    return (e & 31u) + ((x >= __uint_as_float(e)) ? 1u : 0u);
}

// ---------------------------------------------------------------------------
__global__ void __launch_bounds__(TPB) auc_main_kernel(
    const float* __restrict__ outp, const int* __restrict__ target,
    int total4, int n, int C)
{
    extern __shared__ unsigned smem[];
    unsigned* s_lut  = smem;                        // LUTN*32 words (32 KB)
    unsigned* s_hist = smem + LUTN * 32;            // 8 warps x 32 bins x 32 lanes
    unsigned* s_ht   = s_hist + HIST_WORDS;         // 32 words

    const int      tid  = threadIdx.x;
    const unsigned lane = tid & 31u;
    const int      wid  = tid >> 5;

    // Zero hist + s_ht (contiguous).
    for (int i = tid; i < HIST_WORDS + 32; i += TPB) s_hist[i] = 0u;

    // Build packed LUT cell tid, write 32 swizzled replicas (conflict-free STS).
    {
        float cl = -3.5f + (float)tid * (7.0f / 256.0f);
        int base = 0;
#pragma unroll
        for (int k = 0; k < 29; k++) base += (c_xt[k] <= cl) ? 1 : 0;
        unsigned pb = (base < 29)
            ? ((__float_as_uint(c_xt[base]) & 0xFFFFFFE0u) | (unsigned)base)
            : (0x7F800000u | 29u);                  // NaN: x>=NaN false, bin=29
#pragma unroll
        for (int r = 0; r < 32; r++)
            s_lut[(tid << 5) + ((r + tid) & 31)] = pb;
    }
    __syncthreads();

    const unsigned* __restrict__ lutl = s_lut + lane;
    unsigned* __restrict__ hl = s_hist + (wid << 10) + lane;   // own column

    // ---- True-class pre-pass (scattered gather, ~4.4 rows/thread).
    for (int r = blockIdx.x * TPB + tid; r < n; r += GRID * TPB) {
        const int   t = target[r];
        const float x = outp[r * C + t];
        atomicAdd(&s_ht[calc_bin(x, lutl)], 1u);
    }

    // ---- Main streaming pass: 4x float4 per iter, all LDGs unconditional and
    // back-to-back (MLP_p1 = 4); ALL 16 bins computed before ANY smem RMW so
    // the LUT reads never sit behind potentially-aliasing histogram STSs.
    const float4* __restrict__ out4 = (const float4*)outp;
    const int stride = GRID * TPB;
    int v = blockIdx.x * TPB + tid;

    for (; v + 3 * stride < total4; v += 4 * stride) {
        const float4 dA = out4[v];
        const float4 dB = out4[v +     stride];
        const float4 dC = out4[v + 2 * stride];
        const float4 dD = out4[v + 3 * stride];

        unsigned b[16];
        b[0]  = calc_bin(dA.x, lutl); b[1]  = calc_bin(dA.y, lutl);
        b[2]  = calc_bin(dA.z, lutl); b[3]  = calc_bin(dA.w, lutl);
        b[4]  = calc_bin(dB.x, lutl); b[5]  = calc_bin(dB.y, lutl);
        b[6]  = calc_bin(dB.z, lutl); b[7]  = calc_bin(dB.w, lutl);
        b[8]  = calc_bin(dC.x, lutl); b[9]  = calc_bin(dC.y, lutl);
        b[10] = calc_bin(dC.z, lutl); b[11] = calc_bin(dC.w, lutl);
        b[12] = calc_bin(dD.x, lutl); b[13] = calc_bin(dD.y, lutl);
        b[14] = calc_bin(dD.z, lutl); b[15] = calc_bin(dD.w, lutl);

#pragma unroll
        for (int j = 0; j < 16; j++)
            hl[b[j] << 5] += 1u;
    }
    for (; v < total4; v += stride) {               // tail: <= 3 float4s
        const float4 d = out4[v];
        unsigned b0 = calc_bin(d.x, lutl), b1 = calc_bin(d.y, lutl);
        unsigned b2 = calc_bin(d.z, lutl), b3 = calc_bin(d.w, lutl);
        hl[b0 << 5] += 1u;  hl[b1 << 5] += 1u;
        hl[b2 << 5] += 1u;  hl[b3 << 5] += 1u;
    }

    __syncthreads();

    // ---- Block reduction: thread (w=wid, b=lane) sums 32 lane-columns of
    // warp w's bin b, swizzled so banks are distinct per thread. RED to global.
    {
        const unsigned* row = s_hist + (wid << 10) + ((int)lane << 5);
        unsigned sum = 0;
#pragma unroll
        for (int j = 0; j < 32; j++) sum += row[(j + lane) & 31];
        if (sum) atomicAdd(&g_hist_all[lane], sum);
    }
    if (tid < 32) {
        unsigned t = s_ht[tid];
        if (t) atomicAdd(&g_hist_t[tid], t);
    }
}

// ---------------------------------------------------------------------------
__global__ void auc_finalize_kernel(float* __restrict__ out, int total) {
    if (threadIdx.x != 0) return;

    double t[31], a[31], trues = 0.0;
#pragma unroll 1
    for (int b = 0; b < 31; b++) {
        t[b] = (double)g_hist_t[b];
        a[b] = (double)g_hist_all[b];
        trues += t[b];
    }
    const double falses = (double)total - trues;

    double tp_asc[30], fp_asc[30];
    double ct = 0.0, cf = 0.0;
#pragma unroll 1
    for (int k = 0; k < 30; k++) {
        ct += t[k];
        cf += (a[k] - t[k]);
        tp_asc[k] = trues  - ct;
        fp_asc[k] = falses - cf;
    }

    const double dt = trues  + 1e-8;
    const double df = falses + 1e-8;
    double area = 0.0, pt = 0.0, pf = 0.0;
#pragma unroll 1
    for (int i = 0; i < 30; i++) {
        const double tt = tp_asc[29 - i] / dt;
        const double ff = fp_asc[29 - i] / df;
        const double w  = fabs(ff - pf);
        const double mn = fmin(tt, pt);
        const double mx = fmax(tt, pt);
        area += w * mn + 0.5 * w * (mx - mn);
        pt = tt; pf = ff;
    }
    out[0] = (float)area;
}

// ---------------------------------------------------------------------------
extern "C" void kernel_launch(void* const* d_in, const int* in_sizes, int n_in,
                              void* d_out, int out_size) {
    const float* outp   = (const float*)d_in[0];
    const int*   target = (const int*)d_in[1];
    const int total  = in_sizes[0];      // N*C = 32,000,000
    const int n      = in_sizes[1];      // N   = 500,000
    const int C      = total / n;        // 64
    const int total4 = total / 4;

    cudaFuncSetAttribute(auc_main_kernel,
                         cudaFuncAttributeMaxDynamicSharedMemorySize, SMEM_BYTES);

    auc_init_kernel<<<1, 64>>>();
    auc_main_kernel<<<GRID, TPB, SMEM_BYTES>>>(outp, target, total4, n, C);
    auc_finalize_kernel<<<1, 32>>>((float*)d_out, total);
}